// round 1
// baseline (speedup 1.0000x reference)
#include <cuda_runtime.h>
#include <cuda_bf16.h>
#include <cstdint>

// Problem constants (fixed shapes per metadata)
#define NTOK 65536
#define IN   512
#define OUT  512
#define NE   8
#define NS   64

#define TM 128      // tokens per tile
#define TN 128      // outputs per tile
#define KB 16       // k-chunk
#define MAXT 640    // max row-tiles: sum ceil(count/128) <= 512+64 = 576

// ---------------- device scratch (static globals; no allocation) -------------
__device__ float g_M[(size_t)NS * OUT * IN];   // 64 MB mixed weights
__device__ int   g_counts[NS];
__device__ int   g_cursor[NS];
__device__ int   g_perm[NTOK];
__device__ int   g_tile_sys[MAXT];
__device__ int   g_tile_start[MAXT];
__device__ int   g_tile_rows[MAXT];

// ---------------- small helpers ---------------------------------------------
__device__ __forceinline__ unsigned long long pack2(float a, float b) {
    unsigned long long r;
    asm("mov.b64 %0, {%1, %2};" : "=l"(r) : "f"(a), "f"(b));
    return r;
}
__device__ __forceinline__ void ffma2(unsigned long long& c, unsigned long long a,
                                      unsigned long long b) {
    asm("fma.rn.f32x2 %0, %1, %2, %0;" : "+l"(c) : "l"(a), "l"(b));
}
__device__ __forceinline__ float2 u2f2(unsigned long long v) {
    float2 f;
    asm("mov.b64 {%0, %1}, %2;" : "=f"(f.x), "=f"(f.y) : "l"(v));
    return f;
}

// ---------------- kernel 0: per-launch reset ---------------------------------
__global__ void init_kernel() {
    int tid = threadIdx.x;
    if (tid < NS) g_counts[tid] = 0;
    for (int i = tid; i < MAXT; i += blockDim.x) g_tile_rows[i] = 0;
}

// ---------------- kernel 1: histogram ----------------------------------------
__global__ void hist_kernel(const int* __restrict__ bi) {
    __shared__ int h[NS];
    int tid = threadIdx.x;
    if (tid < NS) h[tid] = 0;
    __syncthreads();
    int n = blockIdx.x * blockDim.x + tid;
    if (n < NTOK) atomicAdd(&h[bi[n]], 1);
    __syncthreads();
    if (tid < NS && h[tid] != 0) atomicAdd(&g_counts[tid], h[tid]);
}

// ---------------- kernel 2: scan + tile table --------------------------------
__global__ void plan_kernel() {
    if (threadIdx.x != 0 || blockIdx.x != 0) return;
    int off = 0;
    int t = 0;
    for (int s = 0; s < NS; ++s) {
        g_cursor[s] = off;
        int c = g_counts[s];
        int nt = (c + TM - 1) / TM;
        for (int k = 0; k < nt; ++k) {
            g_tile_sys[t]   = s;
            g_tile_start[t] = off + k * TM;
            int rem = c - k * TM;
            g_tile_rows[t]  = rem < TM ? rem : TM;
            ++t;
        }
        off += c;
    }
}

// ---------------- kernel 3: scatter tokens into system buckets ---------------
__global__ void scatter_kernel(const int* __restrict__ bi) {
    int n = blockIdx.x * blockDim.x + threadIdx.x;
    if (n < NTOK) {
        int pos = atomicAdd(&g_cursor[bi[n]], 1);
        g_perm[pos] = n;
    }
}

// ---------------- kernel 4: mix weights M[s] = sum_e c[s,e] * W[e] -----------
__global__ __launch_bounds__(256) void mix_kernel(const float* __restrict__ W,
                                                  const float* __restrict__ coeff) {
    __shared__ float sc[NS * NE];
    int tid = threadIdx.x;
    for (int i = tid; i < NS * NE; i += blockDim.x) sc[i] = coeff[i];
    __syncthreads();

    int idx = blockIdx.x * blockDim.x + tid;     // 0 .. OUT*IN/4 - 1 (65536)
    int o  = idx / (IN / 4);
    int i4 = (idx % (IN / 4)) * 4;

    float4 w[NE];
#pragma unroll
    for (int e = 0; e < NE; ++e)
        w[e] = *(const float4*)(W + (size_t)e * OUT * IN + o * IN + i4);

#pragma unroll 4
    for (int s = 0; s < NS; ++s) {
        float4 acc = make_float4(0.f, 0.f, 0.f, 0.f);
#pragma unroll
        for (int e = 0; e < NE; ++e) {
            float c = sc[s * NE + e];
            acc.x = fmaf(c, w[e].x, acc.x);
            acc.y = fmaf(c, w[e].y, acc.y);
            acc.z = fmaf(c, w[e].z, acc.z);
            acc.w = fmaf(c, w[e].w, acc.w);
        }
        *(float4*)(g_M + (size_t)s * OUT * IN + o * IN + i4) = acc;
    }
}

// ---------------- kernel 5: grouped GEMM (fp32, FFMA2 packed) ----------------
// Tile: TM=128 tokens x TN=128 outputs, K=512 in chunks of KB=16, double-buffered.
// 256 threads, each computes an 8x8 microtile as 8x4 packed f32x2 accumulators.
__global__ __launch_bounds__(256, 2) void gemm_kernel(const float* __restrict__ x,
                                                      const float* __restrict__ bias,
                                                      float* __restrict__ out) {
    int bt = blockIdx.x;
    int rows = g_tile_rows[bt];
    if (rows == 0) return;
    int sys       = g_tile_sys[bt];
    int row_start = g_tile_start[bt];
    int col0      = blockIdx.y * TN;

    __shared__ __align__(16) float As[2][KB][TM];
    __shared__ __align__(16) float Bs[2][KB][TN];

    int tid = threadIdx.x;

    // --- loader assignment: each thread loads 2 A-rows and 2 B-rows (float4) ---
    int l_row0 = tid >> 2;            // 0..63
    int l_row1 = l_row0 + 64;         // 64..127
    int l_k    = (tid & 3) * 4;       // 0,4,8,12 within k-chunk

    const float* M  = g_M + (size_t)sys * OUT * IN;
    const float* bp0 = M + (size_t)(col0 + l_row0) * IN + l_k;
    const float* bp1 = M + (size_t)(col0 + l_row1) * IN + l_k;

    int tok0 = (l_row0 < rows) ? g_perm[row_start + l_row0] : -1;
    int tok1 = (l_row1 < rows) ? g_perm[row_start + l_row1] : -1;
    const float* ap0 = (tok0 >= 0) ? (x + (size_t)tok0 * IN + l_k) : nullptr;
    const float* ap1 = (tok1 >= 0) ? (x + (size_t)tok1 * IN + l_k) : nullptr;

    int tx4 = (tid & 15) * 4;
    int ty4 = (tid >> 4) * 4;

    unsigned long long acc[8][4];
#pragma unroll
    for (int i = 0; i < 8; ++i)
#pragma unroll
        for (int j = 0; j < 4; ++j) acc[i][j] = 0ull;

    float4 fa0, fa1, fb0, fb1;
    const float4 z4 = make_float4(0.f, 0.f, 0.f, 0.f);

    auto fetch = [&](int k0) {
        fa0 = ap0 ? *(const float4*)(ap0 + k0) : z4;
        fa1 = ap1 ? *(const float4*)(ap1 + k0) : z4;
        fb0 = *(const float4*)(bp0 + k0);
        fb1 = *(const float4*)(bp1 + k0);
    };
    auto stage = [&](int buf) {
        As[buf][l_k + 0][l_row0] = fa0.x;
        As[buf][l_k + 1][l_row0] = fa0.y;
        As[buf][l_k + 2][l_row0] = fa0.z;
        As[buf][l_k + 3][l_row0] = fa0.w;
        As[buf][l_k + 0][l_row1] = fa1.x;
        As[buf][l_k + 1][l_row1] = fa1.y;
        As[buf][l_k + 2][l_row1] = fa1.z;
        As[buf][l_k + 3][l_row1] = fa1.w;
        Bs[buf][l_k + 0][l_row0] = fb0.x;
        Bs[buf][l_k + 1][l_row0] = fb0.y;
        Bs[buf][l_k + 2][l_row0] = fb0.z;
        Bs[buf][l_k + 3][l_row0] = fb0.w;
        Bs[buf][l_k + 0][l_row1] = fb1.x;
        Bs[buf][l_k + 1][l_row1] = fb1.y;
        Bs[buf][l_k + 2][l_row1] = fb1.z;
        Bs[buf][l_k + 3][l_row1] = fb1.w;
    };
    auto compute = [&](int buf) {
#pragma unroll
        for (int kk = 0; kk < KB; ++kk) {
            float4 A0 = *(const float4*)&As[buf][kk][ty4];
            float4 A1 = *(const float4*)&As[buf][kk][64 + ty4];
            ulonglong2 B0 = *(const ulonglong2*)&Bs[buf][kk][tx4];
            ulonglong2 B1 = *(const ulonglong2*)&Bs[buf][kk][64 + tx4];
            unsigned long long b[4] = {B0.x, B0.y, B1.x, B1.y};
            float a[8] = {A0.x, A0.y, A0.z, A0.w, A1.x, A1.y, A1.z, A1.w};
#pragma unroll
            for (int i = 0; i < 8; ++i) {
                unsigned long long a2 = pack2(a[i], a[i]);
#pragma unroll
                for (int j = 0; j < 4; ++j) ffma2(acc[i][j], a2, b[j]);
            }
        }
    };

    fetch(0);
    stage(0);
    __syncthreads();

#pragma unroll 1
    for (int c = 0; c < IN / KB; ++c) {
        int buf = c & 1;
        if (c + 1 < IN / KB) fetch((c + 1) * KB);
        compute(buf);
        if (c + 1 < IN / KB) stage(buf ^ 1);
        __syncthreads();
    }

    // ---------------- epilogue: bias + scatter to out ------------------------
    float4 bw0 = *(const float4*)(bias + col0 + tx4);
    float4 bw1 = *(const float4*)(bias + col0 + 64 + tx4);

#pragma unroll
    for (int u = 0; u < 2; ++u) {
#pragma unroll
        for (int v = 0; v < 4; ++v) {
            int rl = u * 64 + ty4 + v;
            if (rl < rows) {
                int tok = g_perm[row_start + rl];
                float* orow = out + (size_t)tok * OUT + col0;
                int i = u * 4 + v;
                float2 p0 = u2f2(acc[i][0]);
                float2 p1 = u2f2(acc[i][1]);
                float2 p2 = u2f2(acc[i][2]);
                float2 p3 = u2f2(acc[i][3]);
                float4 r0 = make_float4(p0.x + bw0.x, p0.y + bw0.y,
                                        p1.x + bw0.z, p1.y + bw0.w);
                float4 r1 = make_float4(p2.x + bw1.x, p2.y + bw1.y,
                                        p3.x + bw1.z, p3.y + bw1.w);
                *(float4*)(orow + tx4)      = r0;
                *(float4*)(orow + 64 + tx4) = r1;
            }
        }
    }
}

// ---------------- launch -----------------------------------------------------
extern "C" void kernel_launch(void* const* d_in, const int* in_sizes, int n_in,
                              void* d_out, int out_size) {
    const float* x     = (const float*)d_in[0];
    const float* coeff = (const float*)d_in[1];
    const int*   bidx  = (const int*)d_in[2];
    const float* W     = (const float*)d_in[3];
    const float* bias  = (const float*)d_in[4];
    float*       out   = (float*)d_out;

    init_kernel<<<1, 256>>>();
    hist_kernel<<<NTOK / 256, 256>>>(bidx);
    plan_kernel<<<1, 1>>>();
    scatter_kernel<<<NTOK / 256, 256>>>(bidx);
    mix_kernel<<<(OUT * IN / 4) / 256, 256>>>(W, coeff);
    gemm_kernel<<<dim3(MAXT, OUT / TN), 256>>>(x, bias, out);
}

// round 3
// speedup vs baseline: 1.7108x; 1.7108x over previous
#include <cuda_runtime.h>
#include <cuda_bf16.h>
#include <cstdint>

// Problem constants
#define NTOK 65536
#define IN   512
#define OUT  512
#define NE   8
#define NS   64

// GEMM tiling
#define TM 128
#define TN 256
#define KC 32
#define NCHUNK (IN / KC)          // 16
#define MAXT 576                  // sum ceil(c/128) <= 512+64
#define LDSS 80                   // smem row stride (bytes): conflict-free for ldmatrix

#define A_PLANE (TM * LDSS)       // 10240
#define B_PLANE (TN * LDSS)       // 20480
#define OFF_B   (2 * A_PLANE)
#define STAGE_BYTES (2 * A_PLANE + 2 * B_PLANE)   // 61440
#define STAGES 3
#define OFF_PERM (STAGES * STAGE_BYTES)           // 184320
#define GSMEM (OFF_PERM + 512)                    // 184832

// ---------------- device scratch (static; no allocation) ---------------------
__device__ __nv_bfloat16 g_xh[(size_t)NTOK * IN];
__device__ __nv_bfloat16 g_xl[(size_t)NTOK * IN];
__device__ __nv_bfloat16 g_Mh[(size_t)NS * OUT * IN];
__device__ __nv_bfloat16 g_Ml[(size_t)NS * OUT * IN];
__device__ int g_counts[NS];
__device__ int g_cursor[NS];
__device__ int g_perm[NTOK];
__device__ int g_tile_sys[MAXT];
__device__ int g_tile_start[MAXT];
__device__ int g_tile_rows[MAXT];

// ---------------- helpers -----------------------------------------------------
__device__ __forceinline__ uint32_t smem_u32(const void* p) {
    uint32_t a;
    asm("{ .reg .u64 t; cvta.to.shared.u64 t, %1; cvt.u32.u64 %0, t; }"
        : "=r"(a) : "l"(p));
    return a;
}
__device__ __forceinline__ void cpa16(uint32_t dst, const void* src) {
    asm volatile("cp.async.cg.shared.global [%0], [%1], 16;"
                 :: "r"(dst), "l"(src) : "memory");
}
__device__ __forceinline__ void ldsm4(uint32_t* r, uint32_t addr) {
    asm volatile("ldmatrix.sync.aligned.m8n8.x4.shared.b16 {%0,%1,%2,%3}, [%4];"
                 : "=r"(r[0]), "=r"(r[1]), "=r"(r[2]), "=r"(r[3]) : "r"(addr));
}
__device__ __forceinline__ void mma16816(float* c, const uint32_t* a,
                                         uint32_t b0, uint32_t b1) {
    asm volatile(
        "mma.sync.aligned.m16n8k16.row.col.f32.bf16.bf16.f32 "
        "{%0,%1,%2,%3}, {%4,%5,%6,%7}, {%8,%9}, {%0,%1,%2,%3};"
        : "+f"(c[0]), "+f"(c[1]), "+f"(c[2]), "+f"(c[3])
        : "r"(a[0]), "r"(a[1]), "r"(a[2]), "r"(a[3]), "r"(b0), "r"(b1));
}
// fp32x4 -> bf16 hi/lo planes (packed as uint2 each = 4 bf16)
__device__ __forceinline__ void split4(float4 v, uint2& hi, uint2& lo) {
    __nv_bfloat162 h01 = __floats2bfloat162_rn(v.x, v.y);
    __nv_bfloat162 h23 = __floats2bfloat162_rn(v.z, v.w);
    float2 f01 = __bfloat1622float2(h01);
    float2 f23 = __bfloat1622float2(h23);
    __nv_bfloat162 l01 = __floats2bfloat162_rn(v.x - f01.x, v.y - f01.y);
    __nv_bfloat162 l23 = __floats2bfloat162_rn(v.z - f23.x, v.w - f23.y);
    hi = make_uint2(*(uint32_t*)&h01, *(uint32_t*)&h23);
    lo = make_uint2(*(uint32_t*)&l01, *(uint32_t*)&l23);
}

// ---------------- kernel 0: reset ---------------------------------------------
__global__ void init_kernel() {
    if (threadIdx.x < NS) g_counts[threadIdx.x] = 0;
}

// ---------------- kernel 1: histogram (block-aggregated) ----------------------
__global__ void hist_kernel(const int* __restrict__ bi) {
    __shared__ int h[NS];
    int tid = threadIdx.x;
    if (tid < NS) h[tid] = 0;
    __syncthreads();
    int n = blockIdx.x * blockDim.x + tid;
    atomicAdd(&h[bi[n]], 1);
    __syncthreads();
    if (tid < NS && h[tid] != 0) atomicAdd(&g_counts[tid], h[tid]);
}

// ---------------- kernel 2: scan + tile table ---------------------------------
__global__ void plan_kernel() {
    __shared__ int cnt[NS], offs[NS], tbase[NS];
    int tid = threadIdx.x;
    if (tid < NS) cnt[tid] = g_counts[tid];
    __syncthreads();
    if (tid == 0) {
        int off = 0, tb = 0;
        for (int s = 0; s < NS; ++s) {
            offs[s] = off; tbase[s] = tb;
            off += cnt[s];
            tb  += (cnt[s] + TM - 1) / TM;
        }
    }
    __syncthreads();
    for (int i = tid; i < MAXT; i += blockDim.x) g_tile_rows[i] = 0;
    __syncthreads();
    if (tid < NS) {
        int s = tid, c = cnt[s], nt = (c + TM - 1) / TM;
        int tb = tbase[s], off = offs[s];
        g_cursor[s] = off;
        for (int k = 0; k < nt; ++k) {
            g_tile_sys[tb + k]   = s;
            g_tile_start[tb + k] = off + k * TM;
            int rem = c - k * TM;
            g_tile_rows[tb + k]  = rem < TM ? rem : TM;
        }
    }
}

// ---------------- kernel 3: scatter (block-aggregated) ------------------------
__global__ void scatter_kernel(const int* __restrict__ bi) {
    __shared__ int lc[NS], lbase[NS];
    int tid = threadIdx.x;
    if (tid < NS) lc[tid] = 0;
    __syncthreads();
    int n = blockIdx.x * blockDim.x + tid;
    int s = bi[n];
    int r = atomicAdd(&lc[s], 1);
    __syncthreads();
    if (tid < NS && lc[tid] > 0) lbase[tid] = atomicAdd(&g_cursor[tid], lc[tid]);
    __syncthreads();
    g_perm[lbase[s] + r] = n;
}

// ---------------- kernel 4: gather + split x into bf16 hi/lo planes -----------
__global__ __launch_bounds__(256) void prep_x(const float* __restrict__ x) {
    int idx = blockIdx.x * blockDim.x + threadIdx.x;   // over NTOK * 128
    int row = idx >> 7;          // permuted row id
    int q   = idx & 127;         // float4 index within row
    int tok = g_perm[row];
    float4 v = ((const float4*)(x + (size_t)tok * IN))[q];
    uint2 hi, lo;
    split4(v, hi, lo);
    ((uint2*)(g_xh + (size_t)row * IN))[q] = hi;
    ((uint2*)(g_xl + (size_t)row * IN))[q] = lo;
}

// ---------------- kernel 5: mix weights -> bf16 hi/lo planes ------------------
__global__ __launch_bounds__(256) void mix_kernel(const float* __restrict__ W,
                                                  const float* __restrict__ coeff) {
    __shared__ float sc[NS * NE];
    int tid = threadIdx.x;
    for (int i = tid; i < NS * NE; i += blockDim.x) sc[i] = coeff[i];
    __syncthreads();

    int idx = blockIdx.x * blockDim.x + tid;   // over OUT*IN/4 = 65536
    int o  = idx >> 7;
    int q  = idx & 127;
    int i4 = q * 4;

    float4 w[NE];
#pragma unroll
    for (int e = 0; e < NE; ++e)
        w[e] = *(const float4*)(W + (size_t)e * OUT * IN + o * IN + i4);

#pragma unroll 4
    for (int s = 0; s < NS; ++s) {
        float4 acc = make_float4(0.f, 0.f, 0.f, 0.f);
#pragma unroll
        for (int e = 0; e < NE; ++e) {
            float c = sc[s * NE + e];
            acc.x = fmaf(c, w[e].x, acc.x);
            acc.y = fmaf(c, w[e].y, acc.y);
            acc.z = fmaf(c, w[e].z, acc.z);
            acc.w = fmaf(c, w[e].w, acc.w);
        }
        uint2 hi, lo;
        split4(acc, hi, lo);
        ((uint2*)(g_Mh + (size_t)(s * OUT + o) * IN))[q] = hi;
        ((uint2*)(g_Ml + (size_t)(s * OUT + o) * IN))[q] = lo;
    }
}

// ---------------- kernel 6: grouped GEMM via mma.sync bf16 (3-pass split) -----
// CTA: 128 tokens x 256 outputs; 8 warps (2x4), warp tile 64x64.
// K=512 in 16 chunks of 32; 3-stage cp.async pipeline.
__global__ __launch_bounds__(256, 1) void gemm_kernel(const float* __restrict__ bias,
                                                      float* __restrict__ out) {
    int bt = blockIdx.x;
    int rows = g_tile_rows[bt];
    if (rows == 0) return;
    int sys       = g_tile_sys[bt];
    int row_start = g_tile_start[bt];
    int col0      = blockIdx.y * TN;

    extern __shared__ __align__(16) char smem[];
    uint32_t sm = smem_u32(smem);
    int tid = threadIdx.x, lane = tid & 31, wid = tid >> 5;
    int wm = wid >> 2, wn = wid & 3;

    // cache perm slice for epilogue scatter
    int* sperm = (int*)(smem + OFF_PERM);
    if (tid < TM) {
        int rsi = row_start + tid;
        if (rsi > NTOK - 1) rsi = NTOK - 1;
        sperm[tid] = g_perm[rsi];
    }

    // loader indices: thread -> (row, 16B-seg)
    int arow = tid >> 2;
    int ac   = tid & 3;
    size_t sysbase = (size_t)sys * OUT * IN;

    auto load_chunk = [&](int stage, int k0) {
        uint32_t sb = sm + stage * STAGE_BYTES;
#pragma unroll
        for (int h = 0; h < 2; ++h) {
            int row = arow + h * 64;
            int srcrow = row_start + row;
            if (srcrow > NTOK - 1) srcrow = NTOK - 1;
            size_t goff = (size_t)srcrow * IN + k0 + ac * 8;
            cpa16(sb + 0 * A_PLANE + row * LDSS + ac * 16, g_xh + goff);
            cpa16(sb + 1 * A_PLANE + row * LDSS + ac * 16, g_xl + goff);
        }
#pragma unroll
        for (int h = 0; h < 4; ++h) {
            int row = arow + h * 64;
            size_t goff = sysbase + (size_t)(col0 + row) * IN + k0 + ac * 8;
            cpa16(sb + OFF_B + 0 * B_PLANE + row * LDSS + ac * 16, g_Mh + goff);
            cpa16(sb + OFF_B + 1 * B_PLANE + row * LDSS + ac * 16, g_Ml + goff);
        }
        asm volatile("cp.async.commit_group;" ::: "memory");
    };

    float acc[4][8][4];
#pragma unroll
    for (int mf = 0; mf < 4; ++mf)
#pragma unroll
        for (int nf = 0; nf < 8; ++nf)
#pragma unroll
            for (int r = 0; r < 4; ++r) acc[mf][nf][r] = 0.f;

    load_chunk(0, 0);
    load_chunk(1, KC);

    int lrow = lane & 15, kseg = lane >> 4;
    uint32_t a_base = (uint32_t)((wm * 64 + lrow) * LDSS + kseg * 16);
    uint32_t b_base = (uint32_t)(OFF_B + (wn * 64 + lrow) * LDSS + kseg * 16);

#pragma unroll 1
    for (int c = 0; c < NCHUNK; ++c) {
        if (c < NCHUNK - 1) asm volatile("cp.async.wait_group 1;" ::: "memory");
        else                asm volatile("cp.async.wait_group 0;" ::: "memory");
        __syncthreads();
        uint32_t sb = sm + (c % STAGES) * STAGE_BYTES;

#pragma unroll
        for (int kk = 0; kk < 2; ++kk) {
            uint32_t ah[4][4], al[4][4], bb[4][4];
#pragma unroll
            for (int mf = 0; mf < 4; ++mf) {
                uint32_t ad = sb + a_base + mf * 16 * LDSS + kk * 32;
                ldsm4(ah[mf], ad);
                ldsm4(al[mf], ad + A_PLANE);
            }
#pragma unroll
            for (int bf = 0; bf < 4; ++bf)
                ldsm4(bb[bf], sb + b_base + bf * 16 * LDSS + kk * 32);
            // pass 1: Ah * Bh
#pragma unroll
            for (int mf = 0; mf < 4; ++mf)
#pragma unroll
                for (int nf = 0; nf < 8; ++nf)
                    mma16816(acc[mf][nf], ah[mf],
                             bb[nf >> 1][nf & 1], bb[nf >> 1][(nf & 1) + 2]);
            // pass 2: Al * Bh
#pragma unroll
            for (int mf = 0; mf < 4; ++mf)
#pragma unroll
                for (int nf = 0; nf < 8; ++nf)
                    mma16816(acc[mf][nf], al[mf],
                             bb[nf >> 1][nf & 1], bb[nf >> 1][(nf & 1) + 2]);
            // load B lo, pass 3: Ah * Bl
#pragma unroll
            for (int bf = 0; bf < 4; ++bf)
                ldsm4(bb[bf], sb + b_base + bf * 16 * LDSS + kk * 32 + B_PLANE);
#pragma unroll
            for (int mf = 0; mf < 4; ++mf)
#pragma unroll
                for (int nf = 0; nf < 8; ++nf)
                    mma16816(acc[mf][nf], ah[mf],
                             bb[nf >> 1][nf & 1], bb[nf >> 1][(nf & 1) + 2]);
        }
        if (c + 2 < NCHUNK) load_chunk((c + 2) % STAGES, (c + 2) * KC);
    }

    // ---------------- epilogue: bias + scatter -------------------------------
    int g  = lane >> 2;
    int tc = (lane & 3) * 2;
    const float* bptr = bias + col0 + wn * 64 + tc;
    float2 bv[8];
#pragma unroll
    for (int nf = 0; nf < 8; ++nf)
        bv[nf] = make_float2(bptr[nf * 8], bptr[nf * 8 + 1]);

#pragma unroll
    for (int mf = 0; mf < 4; ++mf) {
#pragma unroll
        for (int rh = 0; rh < 2; ++rh) {
            int lr = wm * 64 + mf * 16 + rh * 8 + g;
            if (lr < rows) {
                float* orow = out + (size_t)sperm[lr] * OUT + col0 + wn * 64 + tc;
#pragma unroll
                for (int nf = 0; nf < 8; ++nf) {
                    float2 v = make_float2(acc[mf][nf][rh * 2]     + bv[nf].x,
                                           acc[mf][nf][rh * 2 + 1] + bv[nf].y);
                    *(float2*)(orow + nf * 8) = v;
                }
            }
        }
    }
}

// ---------------- launch -----------------------------------------------------
extern "C" void kernel_launch(void* const* d_in, const int* in_sizes, int n_in,
                              void* d_out, int out_size) {
    const float* x     = (const float*)d_in[0];
    const float* coeff = (const float*)d_in[1];
    const int*   bidx  = (const int*)d_in[2];
    const float* W     = (const float*)d_in[3];
    const float* bias  = (const float*)d_in[4];
    float*       out   = (float*)d_out;

    cudaFuncSetAttribute(gemm_kernel, cudaFuncAttributeMaxDynamicSharedMemorySize,
                         GSMEM);

    init_kernel<<<1, 64>>>();
    hist_kernel<<<NTOK / 1024, 1024>>>(bidx);
    plan_kernel<<<1, 256>>>();
    scatter_kernel<<<NTOK / 1024, 1024>>>(bidx);
    prep_x<<<NTOK * (IN / 4) / 256, 256>>>(x);
    mix_kernel<<<(OUT * IN / 4) / 256, 256>>>(W, coeff);
    gemm_kernel<<<dim3(MAXT, OUT / TN), 256, GSMEM>>>(bias, out);
}